// round 2
// baseline (speedup 1.0000x reference)
#include <cuda_runtime.h>
#include <cstdint>

#define N_NODES 100000
#define N_EDGES 1250000
#define F 64
#define K_DIM 128

// Scratch (no allocations allowed in kernel_launch).
__device__ float g_msum[(size_t)N_NODES * F];
__device__ float g_deg[N_NODES];

// ---------------------------------------------------------------------------
// Kernel 1: zero the accumulators (must happen every graph replay).
// ---------------------------------------------------------------------------
__global__ void zero_kernel() {
    int i = blockIdx.x * blockDim.x + threadIdx.x;
    const int msum4 = (N_NODES * F) / 4;   // 1,600,000 float4
    const int deg4  = N_NODES / 4;         // 25,000 float4
    float4 z = make_float4(0.f, 0.f, 0.f, 0.f);
    if (i < msum4) ((float4*)g_msum)[i] = z;
    if (i < deg4)  ((float4*)g_deg)[i]  = z;
}

// ---------------------------------------------------------------------------
// Kernel 2: edge scatter. One thread per (edge, 4-float chunk): 16 threads
// cooperate on one edge's 64-float row. Consecutive threads read consecutive
// float4s of h[src] (coalesced 256B row) and issue red.global.add.v4.f32
// into msum[dst]. h and msum both fit in L2 -> L2-resident RMW.
// NOTE: src/dst are int32 (JAX x64 disabled downcasts the reference's int64).
// ---------------------------------------------------------------------------
__global__ void scatter_kernel(const float* __restrict__ h,
                               const int* __restrict__ src,
                               const int* __restrict__ dst) {
    long long i = (long long)blockIdx.x * blockDim.x + threadIdx.x;
    if (i >= (long long)N_EDGES * 16) return;
    int e = (int)(i >> 4);
    int c = (int)(i & 15);
    int s = src[e];
    int d = dst[e];
    // Defensive: garbage indices become rel_err, not a crash.
    if ((unsigned)s >= N_NODES || (unsigned)d >= N_NODES) return;
    float4 v = ((const float4*)(h + (long long)s * F))[c];
    float* p = g_msum + (long long)d * F + c * 4;
    asm volatile("red.global.add.v4.f32 [%0], {%1,%2,%3,%4};"
                 :: "l"(p), "f"(v.x), "f"(v.y), "f"(v.z), "f"(v.w)
                 : "memory");
    if (c == 0) atomicAdd(&g_deg[d], 1.0f);   // compiles to RED (no return use)
}

// ---------------------------------------------------------------------------
// Kernel 3: fused h_N = msum/max(deg,1), concat, GEMM (x[1x128] @ W^T[128x64])
// + bias. Register-tiled SIMT fp32 GEMM:
//   block = 128 threads, 64 nodes per block.
//   thread (tx = tid%8, ty = tid/8) computes nodes [4*ty..+3] x feats [8*tx..+7]
//   -> 32 accumulators; per k: 1 LDS.128 (x) + 2 LDS.128 (w) + 32 FFMA.
// Smem: Xs[k][node], Ws[k][out] both stride-68 padded (16B-aligned vector
// reads, conflict-free).
// ---------------------------------------------------------------------------
#define NT 64      // nodes per block
#define SMS 68     // smem row stride (floats); 68*4 bytes, 16B aligned
#define GEMM_SMEM_BYTES (2 * K_DIM * SMS * 4)

__global__ __launch_bounds__(128) void gemm_kernel(const float* __restrict__ h,
                                                   const float* __restrict__ W,
                                                   const float* __restrict__ b,
                                                   float* __restrict__ out) {
    extern __shared__ float smem[];
    float* Xs = smem;                    // [K_DIM][SMS] : x transposed, [k][node]
    float* Ws = smem + K_DIM * SMS;      // [K_DIM][SMS] : W transposed, [k][o]

    int tid = threadIdx.x;
    int node0 = blockIdx.x * NT;

    // Load W (64 x 128, row-major [o][k]) transposed into Ws[k][o].
    for (int idx = tid; idx < 64 * K_DIM; idx += 128) {
        int o = idx >> 7;          // 0..63
        int k = idx & 127;         // 0..127
        Ws[k * SMS + o] = W[idx];
    }

    // Load X tile: k<64 -> h[node][k]; k>=64 -> msum[node][k-64] / max(deg,1)
    for (int idx = tid; idx < NT * K_DIM; idx += 128) {
        int n = idx >> 7;
        int k = idx & 127;
        int node = node0 + n;
        float v = 0.f;
        if (node < N_NODES) {
            if (k < 64) {
                v = h[(long long)node * F + k];
            } else {
                float dg = g_deg[node];
                v = g_msum[(long long)node * F + (k - 64)] * (1.0f / fmaxf(dg, 1.0f));
            }
        }
        Xs[k * SMS + n] = v;
    }
    __syncthreads();

    int tx = tid & 7;    // 8 feat-groups of 8
    int ty = tid >> 3;   // 16 node-groups of 4

    float acc[4][8];
#pragma unroll
    for (int n = 0; n < 4; n++)
#pragma unroll
        for (int o = 0; o < 8; o++) acc[n][o] = 0.f;

    const float* xp = Xs + 4 * ty;
    const float* wp = Ws + 8 * tx;

#pragma unroll 4
    for (int k = 0; k < K_DIM; k++) {
        float4 x4 = *(const float4*)(xp + (long long)k * SMS);
        float4 w0 = *(const float4*)(wp + (long long)k * SMS);
        float4 w1 = *(const float4*)(wp + (long long)k * SMS + 4);
        float xv[4] = {x4.x, x4.y, x4.z, x4.w};
        float wv[8] = {w0.x, w0.y, w0.z, w0.w, w1.x, w1.y, w1.z, w1.w};
#pragma unroll
        for (int n = 0; n < 4; n++)
#pragma unroll
            for (int o = 0; o < 8; o++)
                acc[n][o] = fmaf(xv[n], wv[o], acc[n][o]);
    }

    float4 b0 = *(const float4*)(b + 8 * tx);
    float4 b1 = *(const float4*)(b + 8 * tx + 4);

#pragma unroll
    for (int n = 0; n < 4; n++) {
        int node = node0 + 4 * ty + n;
        if (node < N_NODES) {
            float4 r0 = make_float4(acc[n][0] + b0.x, acc[n][1] + b0.y,
                                    acc[n][2] + b0.z, acc[n][3] + b0.w);
            float4 r1 = make_float4(acc[n][4] + b1.x, acc[n][5] + b1.y,
                                    acc[n][6] + b1.z, acc[n][7] + b1.w);
            float* op = out + (long long)node * F + 8 * tx;
            ((float4*)op)[0] = r0;
            ((float4*)op)[1] = r1;
        }
    }
}

// ---------------------------------------------------------------------------
extern "C" void kernel_launch(void* const* d_in, const int* in_sizes, int n_in,
                              void* d_out, int out_size) {
    const float* h   = (const float*)d_in[0];
    const float* W   = (const float*)d_in[1];
    const float* b   = (const float*)d_in[2];
    const int*   src = (const int*)d_in[3];
    const int*   dst = (const int*)d_in[4];
    float* out = (float*)d_out;

    // Opt-in to >48KB dynamic smem for the GEMM kernel (host-side config,
    // idempotent, no stream work).
    cudaFuncSetAttribute(gemm_kernel, cudaFuncAttributeMaxDynamicSharedMemorySize,
                         GEMM_SMEM_BYTES);

    // 1) zero accumulators
    {
        int threads = (N_NODES * F) / 4;   // covers msum4 and deg4
        zero_kernel<<<(threads + 255) / 256, 256>>>();
    }
    // 2) edge scatter
    {
        long long total = (long long)N_EDGES * 16;   // 20,000,000
        int blocks = (int)((total + 255) / 256);
        scatter_kernel<<<blocks, 256>>>(h, src, dst);
    }
    // 3) fused normalize + GEMM + bias
    {
        int blocks = (N_NODES + NT - 1) / NT;        // 1563
        gemm_kernel<<<blocks, 128, GEMM_SMEM_BYTES>>>(h, W, b, out);
    }
}

// round 3
// speedup vs baseline: 1.2267x; 1.2267x over previous
#include <cuda_runtime.h>
#include <cstdint>

#define N_NODES 100000
#define N_EDGES 1250000
#define F 64
#define K_DIM 128

// ---------------- device scratch (no runtime allocation allowed) -----------
__device__ int   g_count[N_NODES];        // in-degree histogram
__device__ int   g_cursor[N_NODES];       // bucket-fill cursors
__device__ int   g_off[N_NODES];          // exclusive prefix of g_count
__device__ int   g_esrc[N_EDGES];         // src ids grouped by dst (CSR)
__device__ float g_hN[(size_t)N_NODES * F]; // normalized neighbor mean

#define SCAN_BLOCK 1024
#define SCAN_NBLK ((N_NODES + SCAN_BLOCK - 1) / SCAN_BLOCK)   // 98
__device__ int g_bsum[SCAN_NBLK];

// ---------------------------------------------------------------------------
// 1) zero the small counters (400 KB total) each replay.
// ---------------------------------------------------------------------------
__global__ void zero_kernel() {
    int i = blockIdx.x * blockDim.x + threadIdx.x;
    const int n4 = N_NODES / 4;   // 25000
    int4 z = make_int4(0, 0, 0, 0);
    if (i < n4) {
        ((int4*)g_count)[i]  = z;
        ((int4*)g_cursor)[i] = z;
    }
}

// ---------------------------------------------------------------------------
// 2) histogram of dst (int atomics, L2-resident 400 KB -> cheap).
// ---------------------------------------------------------------------------
__global__ void hist_kernel(const int* __restrict__ dst) {
    int e = blockIdx.x * blockDim.x + threadIdx.x;
    if (e >= N_EDGES) return;
    int d = dst[e];
    if ((unsigned)d < N_NODES) atomicAdd(&g_count[d], 1);
}

// ---------------------------------------------------------------------------
// 3) exclusive scan of g_count -> g_off  (3 small kernels).
// ---------------------------------------------------------------------------
__global__ void scan1_kernel() {
    __shared__ int s[SCAN_BLOCK];
    int tid = threadIdx.x;
    int i = blockIdx.x * SCAN_BLOCK + tid;
    int v = (i < N_NODES) ? g_count[i] : 0;
    s[tid] = v;
    __syncthreads();
#pragma unroll
    for (int d = 1; d < SCAN_BLOCK; d <<= 1) {
        int t = (tid >= d) ? s[tid - d] : 0;
        __syncthreads();
        s[tid] += t;
        __syncthreads();
    }
    if (i < N_NODES) g_off[i] = s[tid] - v;            // exclusive within block
    if (tid == SCAN_BLOCK - 1) g_bsum[blockIdx.x] = s[tid];  // block total
}

__global__ void scan2_kernel() {   // serial scan of 98 block sums (tiny)
    if (threadIdx.x == 0 && blockIdx.x == 0) {
        int run = 0;
        for (int i = 0; i < SCAN_NBLK; i++) {
            int t = g_bsum[i];
            g_bsum[i] = run;
            run += t;
        }
    }
}

__global__ void scan3_kernel() {
    int i = blockIdx.x * SCAN_BLOCK + threadIdx.x;
    if (i < N_NODES) g_off[i] += g_bsum[blockIdx.x];
}

// ---------------------------------------------------------------------------
// 4) bucket fill: group src ids by dst.
// ---------------------------------------------------------------------------
__global__ void fill_kernel(const int* __restrict__ src,
                            const int* __restrict__ dst) {
    int e = blockIdx.x * blockDim.x + threadIdx.x;
    if (e >= N_EDGES) return;
    int d = dst[e];
    int s = src[e];
    if ((unsigned)d >= N_NODES || (unsigned)s >= N_NODES) return;
    int pos = g_off[d] + atomicAdd(&g_cursor[d], 1);
    if ((unsigned)pos < N_EDGES) g_esrc[pos] = s;
}

// ---------------------------------------------------------------------------
// 5) gather-aggregate: one warp per node. Each lane owns 2 feats (float2).
//    Atomic-free: edges of a node are summed serially in registers, with
//    4-way unroll for MLP>=4 against the 234-cyc L2 hit latency.
//    Writes normalized h_N directly (deg-0 nodes -> 0).
// ---------------------------------------------------------------------------
__global__ __launch_bounds__(256) void agg_kernel(const float* __restrict__ h) {
    int warp = (blockIdx.x * blockDim.x + threadIdx.x) >> 5;
    int lane = threadIdx.x & 31;
    if (warp >= N_NODES) return;
    int off = g_off[warp];
    int deg = g_count[warp];

    float ax = 0.f, ay = 0.f;
    const int lofs = lane * 2;
    int e = 0;
    for (; e + 4 <= deg; e += 4) {
        int s0 = g_esrc[off + e + 0];
        int s1 = g_esrc[off + e + 1];
        int s2 = g_esrc[off + e + 2];
        int s3 = g_esrc[off + e + 3];
        float2 v0 = *(const float2*)(h + (long long)s0 * F + lofs);
        float2 v1 = *(const float2*)(h + (long long)s1 * F + lofs);
        float2 v2 = *(const float2*)(h + (long long)s2 * F + lofs);
        float2 v3 = *(const float2*)(h + (long long)s3 * F + lofs);
        ax += v0.x + v1.x + v2.x + v3.x;
        ay += v0.y + v1.y + v2.y + v3.y;
    }
    for (; e < deg; e++) {
        int s = g_esrc[off + e];
        float2 v = *(const float2*)(h + (long long)s * F + lofs);
        ax += v.x;
        ay += v.y;
    }
    float inv = 1.f / fmaxf((float)deg, 1.f);
    float2 r = make_float2(ax * inv, ay * inv);
    *(float2*)(g_hN + (long long)warp * F + lofs) = r;
}

// ---------------------------------------------------------------------------
// 6) fused concat + GEMM + bias.  x[64x128] @ W^T[128x64].
//    128 threads, 64 nodes/block, 4x8 register tile per thread.
// ---------------------------------------------------------------------------
#define NT 64
#define SMS 68
#define GEMM_SMEM_BYTES (2 * K_DIM * SMS * 4)

__global__ __launch_bounds__(128) void gemm_kernel(const float* __restrict__ h,
                                                   const float* __restrict__ W,
                                                   const float* __restrict__ b,
                                                   float* __restrict__ out) {
    extern __shared__ float smem[];
    float* Xs = smem;                    // [K_DIM][SMS]
    float* Ws = smem + K_DIM * SMS;      // [K_DIM][SMS]

    int tid = threadIdx.x;
    int node0 = blockIdx.x * NT;

    for (int idx = tid; idx < 64 * K_DIM; idx += 128) {
        int o = idx >> 7;
        int k = idx & 127;
        Ws[k * SMS + o] = W[idx];
    }

    for (int idx = tid; idx < NT * K_DIM; idx += 128) {
        int n = idx >> 7;
        int k = idx & 127;
        int node = node0 + n;
        float v = 0.f;
        if (node < N_NODES) {
            if (k < 64) v = h[(long long)node * F + k];
            else        v = g_hN[(long long)node * F + (k - 64)];
        }
        Xs[k * SMS + n] = v;
    }
    __syncthreads();

    int tx = tid & 7;
    int ty = tid >> 3;

    float acc[4][8];
#pragma unroll
    for (int n = 0; n < 4; n++)
#pragma unroll
        for (int o = 0; o < 8; o++) acc[n][o] = 0.f;

    const float* xp = Xs + 4 * ty;
    const float* wp = Ws + 8 * tx;

#pragma unroll 4
    for (int k = 0; k < K_DIM; k++) {
        float4 x4 = *(const float4*)(xp + k * SMS);
        float4 w0 = *(const float4*)(wp + k * SMS);
        float4 w1 = *(const float4*)(wp + k * SMS + 4);
        float xv[4] = {x4.x, x4.y, x4.z, x4.w};
        float wv[8] = {w0.x, w0.y, w0.z, w0.w, w1.x, w1.y, w1.z, w1.w};
#pragma unroll
        for (int n = 0; n < 4; n++)
#pragma unroll
            for (int o = 0; o < 8; o++)
                acc[n][o] = fmaf(xv[n], wv[o], acc[n][o]);
    }

    float4 b0 = *(const float4*)(b + 8 * tx);
    float4 b1 = *(const float4*)(b + 8 * tx + 4);

#pragma unroll
    for (int n = 0; n < 4; n++) {
        int node = node0 + 4 * ty + n;
        if (node < N_NODES) {
            float4 r0 = make_float4(acc[n][0] + b0.x, acc[n][1] + b0.y,
                                    acc[n][2] + b0.z, acc[n][3] + b0.w);
            float4 r1 = make_float4(acc[n][4] + b1.x, acc[n][5] + b1.y,
                                    acc[n][6] + b1.z, acc[n][7] + b1.w);
            float* op = out + (long long)node * F + 8 * tx;
            ((float4*)op)[0] = r0;
            ((float4*)op)[1] = r1;
        }
    }
}

// ---------------------------------------------------------------------------
extern "C" void kernel_launch(void* const* d_in, const int* in_sizes, int n_in,
                              void* d_out, int out_size) {
    const float* h   = (const float*)d_in[0];
    const float* W   = (const float*)d_in[1];
    const float* b   = (const float*)d_in[2];
    const int*   src = (const int*)d_in[3];
    const int*   dst = (const int*)d_in[4];
    float* out = (float*)d_out;

    cudaFuncSetAttribute(gemm_kernel, cudaFuncAttributeMaxDynamicSharedMemorySize,
                         GEMM_SMEM_BYTES);

    // 1) zero counters (400 KB)
    zero_kernel<<<(N_NODES / 4 + 255) / 256, 256>>>();
    // 2) in-degree histogram
    hist_kernel<<<(N_EDGES + 255) / 256, 256>>>(dst);
    // 3) exclusive scan -> offsets
    scan1_kernel<<<SCAN_NBLK, SCAN_BLOCK>>>();
    scan2_kernel<<<1, 1>>>();
    scan3_kernel<<<SCAN_NBLK, SCAN_BLOCK>>>();
    // 4) group src ids by dst
    fill_kernel<<<(N_EDGES + 255) / 256, 256>>>(src, dst);
    // 5) gather-aggregate (atomic-free) -> normalized h_N
    agg_kernel<<<(N_NODES * 32 + 255) / 256, 256>>>(h);
    // 6) fused concat + GEMM + bias
    gemm_kernel<<<(N_NODES + NT - 1) / NT, 128, GEMM_SMEM_BYTES>>>(h, W, b, out);
}

// round 4
// speedup vs baseline: 1.3256x; 1.0806x over previous
#include <cuda_runtime.h>
#include <cstdint>

#define N_NODES 100000
#define N_EDGES 1250000
#define F 64
#define K_DIM 128

// ---------------- device scratch (no runtime allocation allowed) -----------
__device__ int   g_count[N_NODES];          // in-degree histogram
__device__ int   g_off[N_NODES];            // exclusive prefix of g_count
__device__ int   g_cursor[N_NODES];         // fill cursors (init = g_off)
__device__ int   g_esrc[N_EDGES];           // src ids grouped by dst (CSR)
__device__ float g_hN[(size_t)N_NODES * F]; // normalized neighbor mean

#define SCAN_BLOCK 1024
#define SCAN_NBLK ((N_NODES + SCAN_BLOCK - 1) / SCAN_BLOCK)   // 98
__device__ int g_bsum[SCAN_NBLK];           // per-block totals

// ---------------------------------------------------------------------------
// 1) zero the histogram (400 KB) each replay.
// ---------------------------------------------------------------------------
__global__ void zero_kernel() {
    int i = blockIdx.x * blockDim.x + threadIdx.x;
    if (i < N_NODES / 4) ((int4*)g_count)[i] = make_int4(0, 0, 0, 0);
}

// ---------------------------------------------------------------------------
// 2) histogram of dst.
// ---------------------------------------------------------------------------
__global__ void hist_kernel(const int* __restrict__ dst) {
    int e = blockIdx.x * blockDim.x + threadIdx.x;
    if (e >= N_EDGES) return;
    int d = dst[e];
    if ((unsigned)d < N_NODES) atomicAdd(&g_count[d], 1);
}

// ---------------------------------------------------------------------------
// 3a) block-local exclusive scan; totals -> g_bsum.
// ---------------------------------------------------------------------------
__global__ void scan1_kernel() {
    __shared__ int s[SCAN_BLOCK];
    int tid = threadIdx.x;
    int i = blockIdx.x * SCAN_BLOCK + tid;
    int v = (i < N_NODES) ? g_count[i] : 0;
    s[tid] = v;
    __syncthreads();
#pragma unroll
    for (int d = 1; d < SCAN_BLOCK; d <<= 1) {
        int t = (tid >= d) ? s[tid - d] : 0;
        __syncthreads();
        s[tid] += t;
        __syncthreads();
    }
    if (i < N_NODES) g_off[i] = s[tid] - v;
    if (tid == SCAN_BLOCK - 1) g_bsum[blockIdx.x] = s[tid];
}

// ---------------------------------------------------------------------------
// 3b) add preceding block totals (each block reduces <=98 ints itself),
//     and seed g_cursor = g_off for the fill pass.
// ---------------------------------------------------------------------------
__global__ void scan2_kernel() {
    __shared__ int acc;
    int tid = threadIdx.x;
    if (tid == 0) acc = 0;
    __syncthreads();
    if (tid < blockIdx.x) atomicAdd(&acc, g_bsum[tid]);   // tid < 98
    __syncthreads();
    int i = blockIdx.x * SCAN_BLOCK + tid;
    if (i < N_NODES) {
        int o = g_off[i] + acc;
        g_off[i] = o;
        g_cursor[i] = o;
    }
}

// ---------------------------------------------------------------------------
// 4) bucket fill: group src ids by dst (cursor already holds base offset).
// ---------------------------------------------------------------------------
__global__ void fill_kernel(const int* __restrict__ src,
                            const int* __restrict__ dst) {
    int e = blockIdx.x * blockDim.x + threadIdx.x;
    if (e >= N_EDGES) return;
    int d = dst[e];
    int s = src[e];
    if ((unsigned)d >= N_NODES || (unsigned)s >= N_NODES) return;
    int pos = atomicAdd(&g_cursor[d], 1);
    if ((unsigned)pos < N_EDGES) g_esrc[pos] = s;
}

// ---------------------------------------------------------------------------
// 5) gather-aggregate: HALF-warp (16 lanes) per node, float4 per lane
//    (one LDG.128 x 16 lanes = full 256B row). 4-deep unroll for MLP.
// ---------------------------------------------------------------------------
__global__ __launch_bounds__(256) void agg_kernel(const float* __restrict__ h) {
    int t = blockIdx.x * blockDim.x + threadIdx.x;
    int node = t >> 4;
    int lane = t & 15;
    if (node >= N_NODES) return;
    int off = g_off[node];
    int deg = g_count[node];

    float4 a = make_float4(0.f, 0.f, 0.f, 0.f);
    int e = 0;
    for (; e + 4 <= deg; e += 4) {
        int s0 = g_esrc[off + e + 0];
        int s1 = g_esrc[off + e + 1];
        int s2 = g_esrc[off + e + 2];
        int s3 = g_esrc[off + e + 3];
        float4 v0 = ((const float4*)(h + (long long)s0 * F))[lane];
        float4 v1 = ((const float4*)(h + (long long)s1 * F))[lane];
        float4 v2 = ((const float4*)(h + (long long)s2 * F))[lane];
        float4 v3 = ((const float4*)(h + (long long)s3 * F))[lane];
        a.x += v0.x + v1.x + v2.x + v3.x;
        a.y += v0.y + v1.y + v2.y + v3.y;
        a.z += v0.z + v1.z + v2.z + v3.z;
        a.w += v0.w + v1.w + v2.w + v3.w;
    }
    for (; e < deg; e++) {
        int s = g_esrc[off + e];
        float4 v = ((const float4*)(h + (long long)s * F))[lane];
        a.x += v.x; a.y += v.y; a.z += v.z; a.w += v.w;
    }
    float inv = 1.f / fmaxf((float)deg, 1.f);
    ((float4*)(g_hN + (long long)node * F))[lane] =
        make_float4(a.x * inv, a.y * inv, a.z * inv, a.w * inv);
}

// ---------------------------------------------------------------------------
// 6) tensor-core GEMM: out[64n x 64o] = X[64n x 128k] @ W^T, 3xTF32 split.
//    Block: 128 threads (4 warps), 64 nodes. Warp w owns nodes [16w,16w+16),
//    all 64 out-cols as 8 m16n8 tiles. K loop: 16 steps of k8.
// ---------------------------------------------------------------------------
#define NT 64
#define GSTR 132                         // smem row stride (floats)
#define GEMM_SMEM_BYTES (2 * 64 * GSTR * 4)   // Xs + Ws = 67,584 B

__device__ __forceinline__ void split_tf32(float x, unsigned& hi, unsigned& lo) {
    unsigned h;
    asm("cvt.rna.tf32.f32 %0, %1;" : "=r"(h) : "f"(x));
    float r = x - __uint_as_float(h);
    asm("cvt.rna.tf32.f32 %0, %1;" : "=r"(lo) : "f"(r));
    hi = h;
}

__device__ __forceinline__ void mma_tf32(float d[4], const unsigned a[4],
                                         unsigned b0, unsigned b1) {
    asm volatile(
        "mma.sync.aligned.m16n8k8.row.col.f32.tf32.tf32.f32 "
        "{%0,%1,%2,%3}, {%4,%5,%6,%7}, {%8,%9}, {%0,%1,%2,%3};\n"
        : "+f"(d[0]), "+f"(d[1]), "+f"(d[2]), "+f"(d[3])
        : "r"(a[0]), "r"(a[1]), "r"(a[2]), "r"(a[3]), "r"(b0), "r"(b1));
}

__global__ __launch_bounds__(128) void gemm_kernel(const float* __restrict__ h,
                                                   const float* __restrict__ W,
                                                   const float* __restrict__ b,
                                                   float* __restrict__ out) {
    extern __shared__ float smem[];
    float* Xs = smem;                 // [64 nodes][GSTR] row-major [n][k]
    float* Ws = smem + 64 * GSTR;     // [64 outs ][GSTR] row-major [o][k]

    int tid = threadIdx.x;
    int node0 = blockIdx.x * NT;

    // Ws[o][k] = W[o*128+k]  (coalesced)
    for (int idx = tid; idx < 64 * K_DIM; idx += 128) {
        int o = idx >> 7, k = idx & 127;
        Ws[o * GSTR + k] = W[idx];
    }
    // Xs[n][k]: k<64 -> h, k>=64 -> g_hN (already normalized)
    for (int idx = tid; idx < NT * K_DIM; idx += 128) {
        int n = idx >> 7, k = idx & 127;
        int node = node0 + n;
        float v = 0.f;
        if (node < N_NODES)
            v = (k < 64) ? h[(long long)node * F + k]
                         : g_hN[(long long)node * F + (k - 64)];
        Xs[n * GSTR + k] = v;
    }
    __syncthreads();

    int warp = tid >> 5;
    int lane = tid & 31;
    int g = lane >> 2;       // 0..7
    int t = lane & 3;        // 0..3
    int n0 = warp * 16;

    float acc[8][4];
#pragma unroll
    for (int tl = 0; tl < 8; tl++)
#pragma unroll
        for (int r = 0; r < 4; r++) acc[tl][r] = 0.f;

#pragma unroll 2
    for (int ks = 0; ks < 16; ks++) {
        int k0 = ks * 8;
        const float* xb = Xs + n0 * GSTR + k0;
        // A fragment (m16 x k8), rows {g, g+8}, cols {t, t+4} — bank-conflict-free
        float a0 = xb[g * GSTR + t];
        float a1 = xb[(g + 8) * GSTR + t];
        float a2 = xb[g * GSTR + t + 4];
        float a3 = xb[(g + 8) * GSTR + t + 4];
        unsigned ahi[4], alo[4];
        split_tf32(a0, ahi[0], alo[0]);
        split_tf32(a1, ahi[1], alo[1]);
        split_tf32(a2, ahi[2], alo[2]);
        split_tf32(a3, ahi[3], alo[3]);
#pragma unroll
        for (int tl = 0; tl < 8; tl++) {
            const float* wb = Ws + (tl * 8 + g) * GSTR + k0;  // col = g, k = t/t+4
            float b0f = wb[t];
            float b1f = wb[t + 4];
            unsigned bh0, bl0, bh1, bl1;
            split_tf32(b0f, bh0, bl0);
            split_tf32(b1f, bh1, bl1);
            mma_tf32(acc[tl], ahi, bh0, bh1);   // hi*hi
            mma_tf32(acc[tl], ahi, bl0, bl1);   // hi*lo
            mma_tf32(acc[tl], alo, bh0, bh1);   // lo*hi
        }
    }

    // Epilogue: d0/d1 -> (row g, cols 2t,2t+1), d2/d3 -> (row g+8)
    int nodeA = node0 + n0 + g;
    int nodeB = nodeA + 8;
#pragma unroll
    for (int tl = 0; tl < 8; tl++) {
        int o0 = tl * 8 + 2 * t;
        float bx = b[o0], by = b[o0 + 1];
        if (nodeA < N_NODES)
            *(float2*)(out + (long long)nodeA * F + o0) =
                make_float2(acc[tl][0] + bx, acc[tl][1] + by);
        if (nodeB < N_NODES)
            *(float2*)(out + (long long)nodeB * F + o0) =
                make_float2(acc[tl][2] + bx, acc[tl][3] + by);
    }
}

// ---------------------------------------------------------------------------
extern "C" void kernel_launch(void* const* d_in, const int* in_sizes, int n_in,
                              void* d_out, int out_size) {
    const float* h   = (const float*)d_in[0];
    const float* W   = (const float*)d_in[1];
    const float* b   = (const float*)d_in[2];
    const int*   src = (const int*)d_in[3];
    const int*   dst = (const int*)d_in[4];
    float* out = (float*)d_out;

    cudaFuncSetAttribute(gemm_kernel, cudaFuncAttributeMaxDynamicSharedMemorySize,
                         GEMM_SMEM_BYTES);

    zero_kernel<<<(N_NODES / 4 + 255) / 256, 256>>>();
    hist_kernel<<<(N_EDGES + 255) / 256, 256>>>(dst);
    scan1_kernel<<<SCAN_NBLK, SCAN_BLOCK>>>();
    scan2_kernel<<<SCAN_NBLK, SCAN_BLOCK>>>();
    fill_kernel<<<(N_EDGES + 255) / 256, 256>>>(src, dst);
    agg_kernel<<<((long long)N_NODES * 16 + 255) / 256, 256>>>(h);
    gemm_kernel<<<(N_NODES + NT - 1) / NT, 128, GEMM_SMEM_BYTES>>>(h, W, b, out);
}

// round 6
// speedup vs baseline: 1.3408x; 1.0114x over previous
#include <cuda_runtime.h>
#include <cstdint>

#define N_NODES 100000
#define N_EDGES 1250000
#define F 64
#define K_DIM 128

// ---------------- device scratch ----------------
__device__ int g_count[N_NODES];     // in-degree
__device__ int g_off[N_NODES];       // exclusive prefix
__device__ int g_cursor[N_NODES];    // fill cursors (seeded = g_off)
__device__ int g_esrc[N_EDGES];      // src ids grouped by dst

#define SCAN_BLOCK 1024
#define SCAN_NBLK ((N_NODES + SCAN_BLOCK - 1) / SCAN_BLOCK)   // 98
__device__ int g_bsum[SCAN_NBLK];    // per-block totals

// ---------------------------------------------------------------------------
// 1) zero histogram each replay.
// ---------------------------------------------------------------------------
__global__ void zero_kernel() {
    int i = blockIdx.x * blockDim.x + threadIdx.x;
    if (i < N_NODES / 4) ((int4*)g_count)[i] = make_int4(0, 0, 0, 0);
}

// ---------------------------------------------------------------------------
// 2) histogram of dst, 4 edges/thread.
// ---------------------------------------------------------------------------
__global__ void hist_kernel(const int* __restrict__ dst) {
    int i = blockIdx.x * blockDim.x + threadIdx.x;
    if (i >= N_EDGES / 4) return;
    int4 d = ((const int4*)dst)[i];
    if ((unsigned)d.x < N_NODES) atomicAdd(&g_count[d.x], 1);
    if ((unsigned)d.y < N_NODES) atomicAdd(&g_count[d.y], 1);
    if ((unsigned)d.z < N_NODES) atomicAdd(&g_count[d.z], 1);
    if ((unsigned)d.w < N_NODES) atomicAdd(&g_count[d.w], 1);
}

// ---------------------------------------------------------------------------
// 3a) block-local exclusive scan (shuffle-based); totals -> g_bsum.
//     Strictly terminating (no cross-block waits).
// ---------------------------------------------------------------------------
__global__ __launch_bounds__(SCAN_BLOCK) void scan1_kernel() {
    __shared__ int wsum[32];
    int tid = threadIdx.x;
    int lane = tid & 31, wid = tid >> 5;
    int i = blockIdx.x * SCAN_BLOCK + tid;
    int v = (i < N_NODES) ? g_count[i] : 0;

    int inc = v;
#pragma unroll
    for (int d = 1; d < 32; d <<= 1) {
        int t = __shfl_up_sync(0xffffffffu, inc, d);
        if (lane >= d) inc += t;
    }
    if (lane == 31) wsum[wid] = inc;
    __syncthreads();
    if (wid == 0) {
        int wv = wsum[lane];
        int winc = wv;
#pragma unroll
        for (int d = 1; d < 32; d <<= 1) {
            int t = __shfl_up_sync(0xffffffffu, winc, d);
            if (lane >= d) winc += t;
        }
        wsum[lane] = winc - wv;
    }
    __syncthreads();
    int excl = (inc - v) + wsum[wid];
    if (i < N_NODES) g_off[i] = excl;
    if (tid == SCAN_BLOCK - 1) g_bsum[blockIdx.x] = excl + v;
}

// ---------------------------------------------------------------------------
// 3b) add preceding block totals (each block reduces <=98 ints via smem
//     atomics) and seed g_cursor = g_off. Strictly terminating.
// ---------------------------------------------------------------------------
__global__ __launch_bounds__(SCAN_BLOCK) void scan2_kernel() {
    __shared__ int acc;
    int tid = threadIdx.x;
    if (tid == 0) acc = 0;
    __syncthreads();
    if (tid < blockIdx.x) atomicAdd(&acc, g_bsum[tid]);
    __syncthreads();
    int i = blockIdx.x * SCAN_BLOCK + tid;
    if (i < N_NODES) {
        int o = g_off[i] + acc;
        g_off[i] = o;
        g_cursor[i] = o;
    }
}

// ---------------------------------------------------------------------------
// 4) bucket fill, 4 edges/thread.
// ---------------------------------------------------------------------------
__global__ void fill_kernel(const int* __restrict__ src,
                            const int* __restrict__ dst) {
    int i = blockIdx.x * blockDim.x + threadIdx.x;
    if (i >= N_EDGES / 4) return;
    int4 s4 = ((const int4*)src)[i];
    int4 d4 = ((const int4*)dst)[i];
#pragma unroll
    for (int j = 0; j < 4; j++) {
        int d = (j == 0) ? d4.x : (j == 1) ? d4.y : (j == 2) ? d4.z : d4.w;
        int s = (j == 0) ? s4.x : (j == 1) ? s4.y : (j == 2) ? s4.z : s4.w;
        if ((unsigned)d < N_NODES) {
            int pos = atomicAdd(&g_cursor[d], 1);
            if ((unsigned)pos < N_EDGES)
                g_esrc[pos] = ((unsigned)s < N_NODES) ? s : 0;
        }
    }
}

// ---------------------------------------------------------------------------
// 5) fused aggregate + tensor-core GEMM (3xTF32 split, W-splits precomputed).
//    Block: 128 threads, 64 nodes.
//    Phase A: W -> Whi/Wlo smem (cvt once); h -> Xs[:,0:64];
//             half-warp per node gathers neighbors -> Xs[:,64:128] (mean).
//    Phase B: warp w computes nodes [16w,16w+16) x all 64 outs; inner loop is
//             pure conflict-free LDS + 3 mma per n8 tile.
// ---------------------------------------------------------------------------
#define NT 64
#define GSTR 132
#define GEMM_SMEM_BYTES (3 * 64 * GSTR * 4)   // Xs + Whi + Wlo = 101,376 B

__device__ __forceinline__ void split_tf32(float x, unsigned& hi, unsigned& lo) {
    unsigned h;
    asm("cvt.rna.tf32.f32 %0, %1;" : "=r"(h) : "f"(x));
    float r = x - __uint_as_float(h);
    asm("cvt.rna.tf32.f32 %0, %1;" : "=r"(lo) : "f"(r));
    hi = h;
}

__device__ __forceinline__ void mma_tf32(float d[4], const unsigned a[4],
                                         unsigned b0, unsigned b1) {
    asm volatile(
        "mma.sync.aligned.m16n8k8.row.col.f32.tf32.tf32.f32 "
        "{%0,%1,%2,%3}, {%4,%5,%6,%7}, {%8,%9}, {%0,%1,%2,%3};\n"
        : "+f"(d[0]), "+f"(d[1]), "+f"(d[2]), "+f"(d[3])
        : "r"(a[0]), "r"(a[1]), "r"(a[2]), "r"(a[3]), "r"(b0), "r"(b1));
}

__global__ __launch_bounds__(128) void gemm_kernel(const float* __restrict__ h,
                                                   const float* __restrict__ W,
                                                   const float* __restrict__ b,
                                                   float* __restrict__ out) {
    extern __shared__ float smem[];
    float* Xs  = smem;                  // [64][GSTR]
    float* Whi = smem + 64 * GSTR;      // [64][GSTR] tf32 bits
    float* Wlo = smem + 2 * 64 * GSTR;  // [64][GSTR] tf32 bits

    int tid = threadIdx.x;
    int node0 = blockIdx.x * NT;

    // --- Phase A1: W load + one-time split ---
    for (int idx = tid; idx < 64 * K_DIM; idx += 128) {
        int o = idx >> 7, k = idx & 127;
        float w = W[idx];
        unsigned hi, lo;
        split_tf32(w, hi, lo);
        Whi[o * GSTR + k] = __uint_as_float(hi);
        Wlo[o * GSTR + k] = __uint_as_float(lo);
    }

    // --- Phase A2: self features ---
    for (int idx = tid; idx < NT * 16; idx += 128) {
        int n = idx >> 4, q = idx & 15;
        int node = node0 + n;
        float4 v = make_float4(0.f, 0.f, 0.f, 0.f);
        if (node < N_NODES) v = ((const float4*)(h + (long long)node * F))[q];
        *(float4*)&Xs[n * GSTR + q * 4] = v;
    }

    // --- Phase A3: neighbor mean, half-warp per node ---
    {
        int hw = tid >> 4;
        int ln = tid & 15;
        for (int n = hw; n < NT; n += 8) {
            int node = node0 + n;
            float4 a = make_float4(0.f, 0.f, 0.f, 0.f);
            float inv = 0.f;
            if (node < N_NODES) {
                int off = g_off[node];
                int deg = g_count[node];
                int e = 0;
                for (; e + 4 <= deg; e += 4) {
                    int s0 = g_esrc[off + e + 0];
                    int s1 = g_esrc[off + e + 1];
                    int s2 = g_esrc[off + e + 2];
                    int s3 = g_esrc[off + e + 3];
                    float4 v0 = ((const float4*)(h + (long long)s0 * F))[ln];
                    float4 v1 = ((const float4*)(h + (long long)s1 * F))[ln];
                    float4 v2 = ((const float4*)(h + (long long)s2 * F))[ln];
                    float4 v3 = ((const float4*)(h + (long long)s3 * F))[ln];
                    a.x += v0.x + v1.x + v2.x + v3.x;
                    a.y += v0.y + v1.y + v2.y + v3.y;
                    a.z += v0.z + v1.z + v2.z + v3.z;
                    a.w += v0.w + v1.w + v2.w + v3.w;
                }
                for (; e < deg; e++) {
                    int s = g_esrc[off + e];
                    float4 v = ((const float4*)(h + (long long)s * F))[ln];
                    a.x += v.x; a.y += v.y; a.z += v.z; a.w += v.w;
                }
                inv = 1.f / fmaxf((float)deg, 1.f);
            }
            *(float4*)&Xs[n * GSTR + 64 + ln * 4] =
                make_float4(a.x * inv, a.y * inv, a.z * inv, a.w * inv);
        }
    }
    __syncthreads();

    // --- Phase B: mma mainloop ---
    int warp = tid >> 5;
    int lane = tid & 31;
    int g = lane >> 2;
    int t = lane & 3;
    int n0 = warp * 16;

    float acc[8][4];
#pragma unroll
    for (int tl = 0; tl < 8; tl++)
#pragma unroll
        for (int r = 0; r < 4; r++) acc[tl][r] = 0.f;

#pragma unroll 4
    for (int ks = 0; ks < 16; ks++) {
        int k0 = ks * 8;
        const float* xb = Xs + (n0 + g) * GSTR + k0;
        float a0 = xb[t];
        float a1 = xb[8 * GSTR + t];
        float a2 = xb[t + 4];
        float a3 = xb[8 * GSTR + t + 4];
        unsigned ahi[4], alo[4];
        split_tf32(a0, ahi[0], alo[0]);
        split_tf32(a1, ahi[1], alo[1]);
        split_tf32(a2, ahi[2], alo[2]);
        split_tf32(a3, ahi[3], alo[3]);
#pragma unroll
        for (int tl = 0; tl < 8; tl++) {
            int wrow = (tl * 8 + g) * GSTR + k0;
            unsigned bh0 = __float_as_uint(Whi[wrow + t]);
            unsigned bh1 = __float_as_uint(Whi[wrow + t + 4]);
            unsigned bl0 = __float_as_uint(Wlo[wrow + t]);
            unsigned bl1 = __float_as_uint(Wlo[wrow + t + 4]);
            mma_tf32(acc[tl], ahi, bh0, bh1);
            mma_tf32(acc[tl], ahi, bl0, bl1);
            mma_tf32(acc[tl], alo, bh0, bh1);
        }
    }

    // --- Epilogue ---
    int nodeA = node0 + n0 + g;
    int nodeB = nodeA + 8;
#pragma unroll
    for (int tl = 0; tl < 8; tl++) {
        int o0 = tl * 8 + 2 * t;
        float bx = b[o0], by = b[o0 + 1];
        if (nodeA < N_NODES)
            *(float2*)(out + (long long)nodeA * F + o0) =
                make_float2(acc[tl][0] + bx, acc[tl][1] + by);
        if (nodeB < N_NODES)
            *(float2*)(out + (long long)nodeB * F + o0) =
                make_float2(acc[tl][2] + bx, acc[tl][3] + by);
    }
}

// ---------------------------------------------------------------------------
extern "C" void kernel_launch(void* const* d_in, const int* in_sizes, int n_in,
                              void* d_out, int out_size) {
    const float* h   = (const float*)d_in[0];
    const float* W   = (const float*)d_in[1];
    const float* b   = (const float*)d_in[2];
    const int*   src = (const int*)d_in[3];
    const int*   dst = (const int*)d_in[4];
    float* out = (float*)d_out;

    cudaFuncSetAttribute(gemm_kernel, cudaFuncAttributeMaxDynamicSharedMemorySize,
                         GEMM_SMEM_BYTES);

    zero_kernel<<<(N_NODES / 4 + 255) / 256, 256>>>();
    hist_kernel<<<(N_EDGES / 4 + 255) / 256, 256>>>(dst);
    scan1_kernel<<<SCAN_NBLK, SCAN_BLOCK>>>();
    scan2_kernel<<<SCAN_NBLK, SCAN_BLOCK>>>();
    fill_kernel<<<(N_EDGES / 4 + 255) / 256, 256>>>(src, dst);
    gemm_kernel<<<(N_NODES + NT - 1) / NT, 128, GEMM_SMEM_BYTES>>>(h, W, b, out);
}